// round 2
// baseline (speedup 1.0000x reference)
#include <cuda_runtime.h>
#include <math.h>

#define NN   10000
#define EE   320000
#define TT   12
#define NNZ  (EE + NN)
#define IND  64
#define HID  128
#define EMB  64
#define G3   (3 * EMB)   // 192

// ------------------------- device scratch (no allocs allowed) -------------------------
__device__ int   g_is64;
__device__ float g_deg[NN];
__device__ float g_dinv[NN];
__device__ int   g_cnt[NN];
__device__ int   g_rowptr[NN + 1];
__device__ int   g_wpos[NN];
__device__ int   g_crow[NNZ];
__device__ float g_cw[NNZ];
__device__ float g_AX[(size_t)NN * IND];
__device__ float g_H[(size_t)NN * HID];
__device__ float g_HW[(size_t)NN * EMB];
__device__ float g_Z[(size_t)TT * NN * EMB];
__device__ float g_h[(size_t)NN * EMB];
__device__ float g_gi[(size_t)NN * G3];
__device__ float g_gh[(size_t)NN * G3];

// index accessor: edge_index may be int32 (JAX x64-disabled) or int64
__device__ __forceinline__ int load_idx(const void* ei, long long i) {
    int v;
    if (g_is64) v = (int)((const long long*)ei)[i];
    else        v = ((const int*)ei)[i];
    v = v < 0 ? 0 : (v >= NN ? NN - 1 : v);
    return v;
}

// ------------------------- setup kernels -------------------------
__global__ void k_detect(const int* __restrict__ w) {
    // if data is int64 little-endian with small non-negative values, all odd words are 0
    int all_zero = 1;
    for (int i = 1; i < 2048; i += 2)
        if (w[i] != 0) { all_zero = 0; break; }
    g_is64 = all_zero;
}

__global__ void k_init() {
    int i = blockIdx.x * blockDim.x + threadIdx.x;
    if (i < NN * EMB) g_h[i] = 0.0f;
    if (i < NN) { g_deg[i] = 1.0f; g_cnt[i] = 1; }   // self-loop contributes
}

__global__ void k_count(const void* __restrict__ ei, const float* __restrict__ ew) {
    int e = blockIdx.x * blockDim.x + threadIdx.x;
    if (e >= EE) return;
    int c = load_idx(ei, (long long)EE + e);
    atomicAdd(&g_deg[c], ew[e]);
    atomicAdd(&g_cnt[c], 1);
}

// single-block exclusive scan of g_cnt -> g_rowptr/g_wpos, plus dinv
__global__ void k_scan() {
    __shared__ int sm[1024];
    __shared__ int carry;
    int tid = threadIdx.x;
    if (tid == 0) carry = 0;
    __syncthreads();
    for (int base = 0; base < NN; base += 1024) {
        int idx = base + tid;
        int v = (idx < NN) ? g_cnt[idx] : 0;
        sm[tid] = v;
        __syncthreads();
        for (int off = 1; off < 1024; off <<= 1) {
            int t = (tid >= off) ? sm[tid - off] : 0;
            __syncthreads();
            sm[tid] += t;
            __syncthreads();
        }
        int ex = carry + sm[tid] - v;
        if (idx < NN) {
            g_rowptr[idx] = ex;
            g_wpos[idx]   = ex;
            g_dinv[idx]   = rsqrtf(g_deg[idx]);
        }
        __syncthreads();
        if (tid == 0) carry += sm[1023];
        __syncthreads();
    }
    if (tid == 0) g_rowptr[NN] = carry;
}

__global__ void k_fill(const void* __restrict__ ei, const float* __restrict__ ew) {
    int i = blockIdx.x * blockDim.x + threadIdx.x;
    if (i >= NNZ) return;
    int r, c; float w;
    if (i < EE) {
        r = load_idx(ei, i);
        c = load_idx(ei, (long long)EE + i);
        w = ew[i];
    } else {
        r = c = i - EE; w = 1.0f;
    }
    int p = atomicAdd(&g_wpos[c], 1);
    if (p >= 0 && p < NNZ) {
        g_crow[p] = r;
        g_cw[p]   = w;
    }
}

__global__ void k_norm() {
    int i = blockIdx.x * blockDim.x + threadIdx.x;
    if (i >= NN) return;
    float di = g_dinv[i];
    int e = g_rowptr[i + 1];
    for (int p = g_rowptr[i]; p < e; p++)
        g_cw[p] *= g_dinv[g_crow[p]] * di;
}

// ------------------------- SpMM (width 64), one warp per destination node -------------------------
__global__ void k_spmm64(const float* __restrict__ in, float* __restrict__ out,
                         const float* __restrict__ bias) {
    int w = (blockIdx.x * blockDim.x + threadIdx.x) >> 5;
    int lane = threadIdx.x & 31;
    if (w >= NN) return;
    int s = g_rowptr[w], e = g_rowptr[w + 1];
    float a0 = 0.f, a1 = 0.f;
    int p = s;
    for (; p + 4 <= e; p += 4) {
        int r0 = g_crow[p], r1 = g_crow[p+1], r2 = g_crow[p+2], r3 = g_crow[p+3];
        float w0 = g_cw[p], w1 = g_cw[p+1], w2 = g_cw[p+2], w3 = g_cw[p+3];
        float2 v0 = *(const float2*)(in + (size_t)r0 * 64 + 2 * lane);
        float2 v1 = *(const float2*)(in + (size_t)r1 * 64 + 2 * lane);
        float2 v2 = *(const float2*)(in + (size_t)r2 * 64 + 2 * lane);
        float2 v3 = *(const float2*)(in + (size_t)r3 * 64 + 2 * lane);
        a0 += w0 * v0.x + w1 * v1.x + w2 * v2.x + w3 * v3.x;
        a1 += w0 * v0.y + w1 * v1.y + w2 * v2.y + w3 * v3.y;
    }
    for (; p < e; p++) {
        int r = g_crow[p]; float ww = g_cw[p];
        float2 v = *(const float2*)(in + (size_t)r * 64 + 2 * lane);
        a0 += ww * v.x; a1 += ww * v.y;
    }
    float b0 = 0.f, b1 = 0.f;
    if (bias) { b0 = bias[2 * lane]; b1 = bias[2 * lane + 1]; }
    out[(size_t)w * 64 + 2 * lane]     = a0 + b0;
    out[(size_t)w * 64 + 2 * lane + 1] = a1 + b1;
}

// ------------------------- generic small-GEMM: C[M,NC] = A[M,K] @ B (+bias, +relu) -------------------------
// B in smem (whole matrix, K<=128, NC<=192). 32 rows per block. blockDim = (NC/4)*8.
template<int K, int NC, bool TRANSB, bool RELU>
__global__ void k_gemm(const float* __restrict__ A, const float* __restrict__ B,
                       const float* __restrict__ bias, float* __restrict__ C, int M) {
    extern __shared__ float smem[];
    const int NCP = NC + 4;
    float* Bs = smem;                  // K * NCP
    float* As = smem + K * NCP;        // K * 36
    float* bs = As + K * 36;           // NC
    int tid = threadIdx.x, bd = blockDim.x;
    for (int i = tid; i < K * NC; i += bd) {
        if (TRANSB) { int n = i / K, k = i % K; Bs[k * NCP + n] = B[i]; }   // B is [NC,K]
        else        { int k = i / NC, n = i % NC; Bs[k * NCP + n] = B[i]; } // B is [K,NC]
    }
    for (int i = tid; i < NC; i += bd) bs[i] = bias ? bias[i] : 0.f;
    int row0 = blockIdx.x * 32;
    for (int i = tid; i < 32 * K; i += bd) {
        int r = i / K, k = i % K;
        As[k * 36 + r] = (row0 + r < M) ? A[(size_t)(row0 + r) * K + k] : 0.f;
    }
    __syncthreads();
    const int CG = NC / 4;
    int ty = tid / CG, tx = tid % CG;   // ty in [0,8)
    float acc[4][4] = {};
    #pragma unroll 8
    for (int k = 0; k < K; k++) {
        float4 a = *(const float4*)&As[k * 36 + 4 * ty];
        float4 b = *(const float4*)&Bs[k * NCP + 4 * tx];
        float av[4] = {a.x, a.y, a.z, a.w};
        float bv[4] = {b.x, b.y, b.z, b.w};
        #pragma unroll
        for (int i = 0; i < 4; i++)
            #pragma unroll
            for (int j = 0; j < 4; j++)
                acc[i][j] += av[i] * bv[j];
    }
    #pragma unroll
    for (int i = 0; i < 4; i++) {
        int r = row0 + 4 * ty + i;
        if (r < M) {
            #pragma unroll
            for (int j = 0; j < 4; j++) {
                float v = acc[i][j] + bs[4 * tx + j];
                if (RELU) v = fmaxf(v, 0.f);
                C[(size_t)r * NC + 4 * tx + j] = v;
            }
        }
    }
}

// ------------------------- GRU gate fusion -------------------------
__global__ void k_gate() {
    int i = blockIdx.x * blockDim.x + threadIdx.x;
    if (i >= NN * EMB) return;
    int n = i >> 6, j = i & 63;
    const float* gi = g_gi + (size_t)n * G3;
    const float* gh = g_gh + (size_t)n * G3;
    float r  = 1.f / (1.f + __expf(-(gi[j]       + gh[j])));
    float zg = 1.f / (1.f + __expf(-(gi[64 + j]  + gh[64 + j])));
    float ng = tanhf(gi[128 + j] + r * gh[128 + j]);
    g_h[i] = (1.f - zg) * ng + zg * g_h[i];
}

// ------------------------- decoder: softplus(Z @ Z^T + b), symmetric -------------------------
__device__ __forceinline__ float softplus_f(float x) {
    return fmaxf(x, 0.f) + log1pf(__expf(-fabsf(x)));
}

__global__ __launch_bounds__(256) void k_decoder(const float* __restrict__ Z,
                                                 const float* __restrict__ dec_bias,
                                                 float* __restrict__ out) {
    int bj = blockIdx.x, bi = blockIdx.y;
    if (bi > bj) return;                 // upper triangle only
    extern __shared__ float smem[];
    float* As = smem;                    // [64][132]
    float* Bs = smem + 64 * 132;         // [64][132]
    int tid = threadIdx.x;
    int ri0 = bi * 128, rj0 = bj * 128;
    for (int i = tid; i < 128 * 64; i += 256) {
        int r = i >> 6, k = i & 63;
        As[k * 132 + r] = (ri0 + r < NN) ? Z[(size_t)(ri0 + r) * 64 + k] : 0.f;
        Bs[k * 132 + r] = (rj0 + r < NN) ? Z[(size_t)(rj0 + r) * 64 + k] : 0.f;
    }
    __syncthreads();
    int tx = tid & 15, ty = tid >> 4;
    float acc[8][8] = {};
    #pragma unroll 4
    for (int k = 0; k < 64; k++) {
        const float4* A4 = (const float4*)&As[k * 132];
        const float4* B4 = (const float4*)&Bs[k * 132];
        float4 a0 = A4[ty], a1 = A4[16 + ty];
        float4 b0 = B4[tx], b1 = B4[16 + tx];
        float ar[8] = {a0.x, a0.y, a0.z, a0.w, a1.x, a1.y, a1.z, a1.w};
        float bc[8] = {b0.x, b0.y, b0.z, b0.w, b1.x, b1.y, b1.z, b1.w};
        #pragma unroll
        for (int i = 0; i < 8; i++)
            #pragma unroll
            for (int j = 0; j < 8; j++)
                acc[i][j] += ar[i] * bc[j];
    }
    float db = dec_bias[0];
    int rl[8], cl[8];
    #pragma unroll
    for (int i = 0; i < 8; i++) {
        rl[i] = (i < 4) ? 4 * ty + i : 64 + 4 * ty + (i - 4);
        cl[i] = (i < 4) ? 4 * tx + i : 64 + 4 * tx + (i - 4);
    }
    #pragma unroll
    for (int i = 0; i < 8; i++)
        #pragma unroll
        for (int j = 0; j < 8; j++)
            acc[i][j] = softplus_f(acc[i][j] + db);

    // direct (upper) write: rows from tile bi, cols from tile bj — coalesced
    #pragma unroll
    for (int i = 0; i < 8; i++) {
        int r = ri0 + rl[i];
        if (r < NN) {
            #pragma unroll
            for (int j = 0; j < 8; j++) {
                int c = rj0 + cl[j];
                if (c < NN) out[(size_t)r * NN + c] = acc[i][j];
            }
        }
    }
    if (bi != bj) {
        __syncthreads();
        float* St = smem;                // reuse as [128][129] transposed staging
        #pragma unroll
        for (int i = 0; i < 8; i++)
            #pragma unroll
            for (int j = 0; j < 8; j++)
                St[cl[j] * 129 + rl[i]] = acc[i][j];
        __syncthreads();
        for (int i = tid; i < 128 * 128; i += 256) {
            int cr = i >> 7, cc = i & 127;
            int r = rj0 + cr, c = ri0 + cc;
            if (r < NN && c < NN) out[(size_t)r * NN + c] = St[cr * 129 + cc];
        }
    }
}

__global__ void k_zcopy(float* __restrict__ o) {
    int i = blockIdx.x * blockDim.x + threadIdx.x;
    if (i < NN * EMB) o[i] = g_h[i];
}

// ------------------------- host orchestration -------------------------
extern "C" void kernel_launch(void* const* d_in, const int* in_sizes, int n_in,
                              void* d_out, int out_size) {
    const float* x   = (const float*)d_in[0];
    const void*  ei  = d_in[1];                 // int32 or int64 (runtime-detected)
    const float* ew  = (const float*)d_in[2];
    const float* W1  = (const float*)d_in[3];
    const float* b1  = (const float*)d_in[4];
    const float* W2  = (const float*)d_in[5];
    const float* b2  = (const float*)d_in[6];
    const float* Wih = (const float*)d_in[7];
    const float* Whh = (const float*)d_in[8];
    const float* bih = (const float*)d_in[9];
    const float* bhh = (const float*)d_in[10];
    const float* db  = (const float*)d_in[11];
    float* out = (float*)d_out;

    float *pAX, *pH, *pHW, *pZ, *ph, *pgi, *pgh;
    cudaGetSymbolAddress((void**)&pAX, g_AX);
    cudaGetSymbolAddress((void**)&pH,  g_H);
    cudaGetSymbolAddress((void**)&pHW, g_HW);
    cudaGetSymbolAddress((void**)&pZ,  g_Z);
    cudaGetSymbolAddress((void**)&ph,  g_h);
    cudaGetSymbolAddress((void**)&pgi, g_gi);
    cudaGetSymbolAddress((void**)&pgh, g_gh);

    const size_t s1 = (size_t)(64 * (128 + 4) + 64 * 36 + 128) * 4;   // k_gemm<64,128>
    const size_t s2 = (size_t)(128 * (64 + 4) + 128 * 36 + 64) * 4;   // k_gemm<128,64>
    const size_t s3 = (size_t)(64 * (192 + 4) + 64 * 36 + 192) * 4;   // k_gemm<64,192>
    const size_t sd = (size_t)(2 * 64 * 132) * 4;                     // decoder (>= 128*129*4)

    cudaFuncSetAttribute(k_gemm<64, 128, false, true>,
                         cudaFuncAttributeMaxDynamicSharedMemorySize, (int)s1);
    cudaFuncSetAttribute(k_gemm<128, 64, false, false>,
                         cudaFuncAttributeMaxDynamicSharedMemorySize, (int)s2);
    cudaFuncSetAttribute(k_gemm<64, 192, true, false>,
                         cudaFuncAttributeMaxDynamicSharedMemorySize, (int)s3);
    cudaFuncSetAttribute(k_decoder,
                         cudaFuncAttributeMaxDynamicSharedMemorySize, (int)sd);

    // ---- graph-structure setup (once per launch) ----
    k_detect<<<1, 1>>>((const int*)ei);
    k_init<<<(NN * EMB + 255) / 256, 256>>>();
    k_count<<<(EE + 255) / 256, 256>>>(ei, ew);
    k_scan<<<1, 1024>>>();
    k_fill<<<(NNZ + 255) / 256, 256>>>(ei, ew);
    k_norm<<<(NN + 255) / 256, 256>>>();

    const int gM = (NN + 31) / 32;            // 313 row-tiles
    const int spmmBlocks = (NN * 32 + 255) / 256;

    // ---- encoder: z_t = A @ ((relu((A @ x_t) @ W1 + b1)) @ W2) + b2 ----
    for (int t = 0; t < TT; t++) {
        k_spmm64<<<spmmBlocks, 256>>>(x + (size_t)t * NN * IND, pAX, nullptr);
        k_gemm<64, 128, false, true><<<gM, 256, s1>>>(pAX, W1, b1, pH, NN);
        k_gemm<128, 64, false, false><<<gM, 128, s2>>>(pH, W2, nullptr, pHW, NN);
        k_spmm64<<<spmmBlocks, 256>>>(pHW, pZ + (size_t)t * NN * EMB, b2);
    }

    // ---- GRU ----
    for (int t = 0; t < TT; t++) {
        k_gemm<64, 192, true, false><<<gM, 384, s3>>>(pZ + (size_t)t * NN * EMB, Wih, bih, pgi, NN);
        k_gemm<64, 192, true, false><<<gM, 384, s3>>>(ph, Whh, bhh, pgh, NN);
        k_gate<<<(NN * EMB + 255) / 256, 256>>>();
    }

    // ---- decoder ----
    dim3 dg((NN + 127) / 128, (NN + 127) / 128);   // 79 x 79, lower half early-exits
    k_decoder<<<dg, 256, sd>>>(ph, db, out);
    k_zcopy<<<(NN * EMB + 255) / 256, 256>>>(out + (size_t)NN * NN);
}

// round 3
// speedup vs baseline: 1.0944x; 1.0944x over previous
#include <cuda_runtime.h>
#include <math.h>

#define NN   10000
#define EE   320000
#define TT   12
#define NNZ  (EE + NN)
#define IND  64
#define HID  128
#define EMB  64
#define G3   (3 * EMB)   // 192

// ------------------------- device scratch (no allocs allowed) -------------------------
__device__ int   g_is64;
__device__ float g_deg[NN];
__device__ float g_dinv[NN];
__device__ int   g_cnt[NN];
__device__ int   g_rowptr[NN + 1];
__device__ int   g_wpos[NN];
__device__ int   g_crow[NNZ];
__device__ float g_cw[NNZ];
__device__ float g_AX[(size_t)TT * NN * IND];
__device__ float g_HW[(size_t)TT * NN * EMB];
__device__ float g_Z[(size_t)TT * NN * EMB];
__device__ float g_h[(size_t)NN * EMB];
__device__ float g_gi[(size_t)TT * NN * G3];

// index accessor: edge_index may be int32 (JAX x64-disabled) or int64
__device__ __forceinline__ int load_idx(const void* ei, long long i) {
    int v;
    if (g_is64) v = (int)((const long long*)ei)[i];
    else        v = ((const int*)ei)[i];
    v = v < 0 ? 0 : (v >= NN ? NN - 1 : v);
    return v;
}

// ------------------------- setup kernels -------------------------
__global__ void k_detect(const int* __restrict__ w) {
    int all_zero = 1;
    for (int i = 1; i < 2048; i += 2)
        if (w[i] != 0) { all_zero = 0; break; }
    g_is64 = all_zero;
}

__global__ void k_init() {
    int i = blockIdx.x * blockDim.x + threadIdx.x;
    if (i < NN * EMB) g_h[i] = 0.0f;
    if (i < NN) { g_deg[i] = 1.0f; g_cnt[i] = 1; }   // self-loop contributes
}

__global__ void k_count(const void* __restrict__ ei, const float* __restrict__ ew) {
    int e = blockIdx.x * blockDim.x + threadIdx.x;
    if (e >= EE) return;
    int c = load_idx(ei, (long long)EE + e);
    atomicAdd(&g_deg[c], ew[e]);
    atomicAdd(&g_cnt[c], 1);
}

// single-block scan via warp shuffles
__global__ void k_scan() {
    __shared__ int wsum[32];
    __shared__ int carry;
    int tid = threadIdx.x, lane = tid & 31, wid = tid >> 5;
    if (tid == 0) carry = 0;
    __syncthreads();
    for (int base = 0; base < NN; base += 1024) {
        int idx = base + tid;
        int v = (idx < NN) ? g_cnt[idx] : 0;
        int s = v;
        #pragma unroll
        for (int off = 1; off < 32; off <<= 1) {
            int t = __shfl_up_sync(0xffffffffu, s, off);
            if (lane >= off) s += t;
        }
        if (lane == 31) wsum[wid] = s;
        __syncthreads();
        if (wid == 0) {
            int ws = wsum[lane];
            #pragma unroll
            for (int off = 1; off < 32; off <<= 1) {
                int t = __shfl_up_sync(0xffffffffu, ws, off);
                if (lane >= off) ws += t;
            }
            wsum[lane] = ws;
        }
        __syncthreads();
        int below = (wid > 0) ? wsum[wid - 1] : 0;
        int ex = carry + below + s - v;
        if (idx < NN) {
            g_rowptr[idx] = ex;
            g_wpos[idx]   = ex;
            g_dinv[idx]   = rsqrtf(g_deg[idx]);
        }
        __syncthreads();
        if (tid == 0) carry += wsum[31];
        __syncthreads();
    }
    if (threadIdx.x == 0) g_rowptr[NN] = carry;
}

__global__ void k_fill(const void* __restrict__ ei, const float* __restrict__ ew) {
    int i = blockIdx.x * blockDim.x + threadIdx.x;
    if (i >= NNZ) return;
    int r, c; float w;
    if (i < EE) {
        r = load_idx(ei, i);
        c = load_idx(ei, (long long)EE + i);
        w = ew[i];
    } else {
        r = c = i - EE; w = 1.0f;
    }
    int p = atomicAdd(&g_wpos[c], 1);
    if (p >= 0 && p < NNZ) {
        g_crow[p] = r;
        g_cw[p]   = w;
    }
}

__global__ void k_norm() {
    int i = blockIdx.x * blockDim.x + threadIdx.x;
    if (i >= NN) return;
    float di = g_dinv[i];
    int e = g_rowptr[i + 1];
    for (int p = g_rowptr[i]; p < e; p++)
        g_cw[p] *= g_dinv[g_crow[p]] * di;
}

// ------------------------- batched SpMM (width 64), one warp per (node, t) -------------------------
__global__ void k_spmm64b(const float* __restrict__ in_base, float* __restrict__ out_base,
                          const float* __restrict__ bias) {
    int w = (blockIdx.x * blockDim.x + threadIdx.x) >> 5;
    int lane = threadIdx.x & 31;
    if (w >= NN) return;
    const float* in  = in_base  + (size_t)blockIdx.y * NN * 64;
    float*       out = out_base + (size_t)blockIdx.y * NN * 64;
    int s = g_rowptr[w], e = g_rowptr[w + 1];
    float a0 = 0.f, a1 = 0.f;
    int p = s;
    for (; p + 4 <= e; p += 4) {
        int r0 = g_crow[p], r1 = g_crow[p+1], r2 = g_crow[p+2], r3 = g_crow[p+3];
        float w0 = g_cw[p], w1 = g_cw[p+1], w2 = g_cw[p+2], w3 = g_cw[p+3];
        float2 v0 = *(const float2*)(in + (size_t)r0 * 64 + 2 * lane);
        float2 v1 = *(const float2*)(in + (size_t)r1 * 64 + 2 * lane);
        float2 v2 = *(const float2*)(in + (size_t)r2 * 64 + 2 * lane);
        float2 v3 = *(const float2*)(in + (size_t)r3 * 64 + 2 * lane);
        a0 += w0 * v0.x + w1 * v1.x + w2 * v2.x + w3 * v3.x;
        a1 += w0 * v0.y + w1 * v1.y + w2 * v2.y + w3 * v3.y;
    }
    for (; p < e; p++) {
        int r = g_crow[p]; float ww = g_cw[p];
        float2 v = *(const float2*)(in + (size_t)r * 64 + 2 * lane);
        a0 += ww * v.x; a1 += ww * v.y;
    }
    float b0 = 0.f, b1 = 0.f;
    if (bias) { b0 = bias[2 * lane]; b1 = bias[2 * lane + 1]; }
    out[(size_t)w * 64 + 2 * lane]     = a0 + b0;
    out[(size_t)w * 64 + 2 * lane + 1] = a1 + b1;
}

// ------------------------- fused encoder GEMM: out = relu(A@W1+b1)@W2, batched over t ----------
// A: [T*NN, 64] slices, W1: [64,128], W2: [128,64]. 32 rows/block, 256 threads.
__global__ __launch_bounds__(256) void k_encfuse(const float* __restrict__ Abase,
                                                 const float* __restrict__ W1,
                                                 const float* __restrict__ b1,
                                                 const float* __restrict__ W2,
                                                 float* __restrict__ Obase) {
    extern __shared__ float smem[];
    float* W1s = smem;                         // [64][132]
    float* W2s = W1s + 64 * 132;               // [128][68]
    float* As  = W2s + 128 * 68;               // [64][36]  k-major A tile
    float* Hs  = As + 64 * 36;                 // [128][36] k-major H tile
    float* b1s = Hs + 128 * 36;                // [128]
    int tid = threadIdx.x;
    const float* A = Abase + (size_t)blockIdx.y * NN * 64;
    float*       O = Obase + (size_t)blockIdx.y * NN * 64;
    int row0 = blockIdx.x * 32;

    for (int i = tid; i < 64 * 128; i += 256) {
        int k = i >> 7, n = i & 127;
        W1s[k * 132 + n] = W1[i];
    }
    for (int i = tid; i < 128 * 64; i += 256) {
        int k = i >> 6, n = i & 63;
        W2s[k * 68 + n] = W2[i];
    }
    if (tid < 128) b1s[tid] = b1[tid];
    for (int i = tid; i < 32 * 64; i += 256) {
        int r = i >> 6, k = i & 63;
        As[k * 36 + r] = (row0 + r < NN) ? A[(size_t)(row0 + r) * 64 + k] : 0.f;
    }
    __syncthreads();

    // stage 1: H[32][128] = relu(A@W1 + b1)
    {
        int ty = tid >> 5, tx = tid & 31;      // rows 4*ty.., cols 4*tx..
        float acc[4][4] = {};
        #pragma unroll 8
        for (int k = 0; k < 64; k++) {
            float4 a = *(const float4*)&As[k * 36 + 4 * ty];
            float4 b = *(const float4*)&W1s[k * 132 + 4 * tx];
            float av[4] = {a.x, a.y, a.z, a.w};
            float bv[4] = {b.x, b.y, b.z, b.w};
            #pragma unroll
            for (int i = 0; i < 4; i++)
                #pragma unroll
                for (int j = 0; j < 4; j++)
                    acc[i][j] += av[i] * bv[j];
        }
        #pragma unroll
        for (int j = 0; j < 4; j++) {
            int c = 4 * tx + j;
            float bb = b1s[c];
            #pragma unroll
            for (int i = 0; i < 4; i++)
                Hs[c * 36 + 4 * ty + i] = fmaxf(acc[i][j] + bb, 0.f);
        }
    }
    __syncthreads();

    // stage 2: O[32][64] = H@W2
    {
        int ty = tid >> 4, tx = tid & 15;      // rows 2*ty.., cols 4*tx..
        float acc[2][4] = {};
        #pragma unroll 8
        for (int k = 0; k < 128; k++) {
            float a0 = Hs[k * 36 + 2 * ty];
            float a1 = Hs[k * 36 + 2 * ty + 1];
            float4 b = *(const float4*)&W2s[k * 68 + 4 * tx];
            float bv[4] = {b.x, b.y, b.z, b.w};
            #pragma unroll
            for (int j = 0; j < 4; j++) {
                acc[0][j] += a0 * bv[j];
                acc[1][j] += a1 * bv[j];
            }
        }
        #pragma unroll
        for (int i = 0; i < 2; i++) {
            int r = row0 + 2 * ty + i;
            if (r < NN) {
                #pragma unroll
                for (int j = 0; j < 4; j++)
                    O[(size_t)r * 64 + 4 * tx + j] = acc[i][j];
            }
        }
    }
}

// ------------------------- generic small-GEMM (for batched gi) -------------------------
template<int K, int NC, bool TRANSB, bool RELU>
__global__ void k_gemm(const float* __restrict__ A, const float* __restrict__ B,
                       const float* __restrict__ bias, float* __restrict__ C, int M) {
    extern __shared__ float smem[];
    const int NCP = NC + 4;
    float* Bs = smem;
    float* As = smem + K * NCP;
    float* bs = As + K * 36;
    int tid = threadIdx.x, bd = blockDim.x;
    for (int i = tid; i < K * NC; i += bd) {
        if (TRANSB) { int n = i / K, k = i % K; Bs[k * NCP + n] = B[i]; }
        else        { int k = i / NC, n = i % NC; Bs[k * NCP + n] = B[i]; }
    }
    for (int i = tid; i < NC; i += bd) bs[i] = bias ? bias[i] : 0.f;
    int row0 = blockIdx.x * 32;
    for (int i = tid; i < 32 * K; i += bd) {
        int r = i / K, k = i % K;
        As[k * 36 + r] = (row0 + r < M) ? A[(size_t)(row0 + r) * K + k] : 0.f;
    }
    __syncthreads();
    const int CG = NC / 4;
    int ty = tid / CG, tx = tid % CG;
    float acc[4][4] = {};
    #pragma unroll 8
    for (int k = 0; k < K; k++) {
        float4 a = *(const float4*)&As[k * 36 + 4 * ty];
        float4 b = *(const float4*)&Bs[k * NCP + 4 * tx];
        float av[4] = {a.x, a.y, a.z, a.w};
        float bv[4] = {b.x, b.y, b.z, b.w};
        #pragma unroll
        for (int i = 0; i < 4; i++)
            #pragma unroll
            for (int j = 0; j < 4; j++)
                acc[i][j] += av[i] * bv[j];
    }
    #pragma unroll
    for (int i = 0; i < 4; i++) {
        int r = row0 + 4 * ty + i;
        if (r < M) {
            #pragma unroll
            for (int j = 0; j < 4; j++) {
                float v = acc[i][j] + bs[4 * tx + j];
                if (RELU) v = fmaxf(v, 0.f);
                C[(size_t)r * NC + 4 * tx + j] = v;
            }
        }
    }
}

// ------------------------- fused GRU step: gh = h@Whh^T + bhh ; gate ; h update -------------
// Whh: [192,64] row-major. 32 rows/block, 384 threads.
__global__ __launch_bounds__(384) void k_grustep(const float* __restrict__ Whh,
                                                 const float* __restrict__ bhh,
                                                 const float* __restrict__ gi_t) {
    extern __shared__ float smem[];
    float* Ws  = smem;                     // [64][196]
    float* hs  = Ws + 64 * 196;            // [64][36]  k-major h tile
    float* ghs = hs + 64 * 36;             // [32][196]
    float* bs  = ghs + 32 * 196;           // [192]
    int tid = threadIdx.x;
    int row0 = blockIdx.x * 32;

    for (int i = tid; i < 192 * 64; i += 384) {
        int n = i >> 6, k = i & 63;        // Whh[n][k]
        Ws[k * 196 + n] = Whh[i];
    }
    if (tid < 192) bs[tid] = bhh[tid];
    for (int i = tid; i < 32 * 64; i += 384) {
        int r = i >> 6, k = i & 63;
        hs[k * 36 + r] = (row0 + r < NN) ? g_h[(size_t)(row0 + r) * 64 + k] : 0.f;
    }
    __syncthreads();

    // gh[32][192]
    {
        int ty = tid / 48, tx = tid % 48;  // rows 4*ty.., cols 4*tx..
        float acc[4][4] = {};
        #pragma unroll 8
        for (int k = 0; k < 64; k++) {
            float4 a = *(const float4*)&hs[k * 36 + 4 * ty];
            float4 b = *(const float4*)&Ws[k * 196 + 4 * tx];
            float av[4] = {a.x, a.y, a.z, a.w};
            float bv[4] = {b.x, b.y, b.z, b.w};
            #pragma unroll
            for (int i = 0; i < 4; i++)
                #pragma unroll
                for (int j = 0; j < 4; j++)
                    acc[i][j] += av[i] * bv[j];
        }
        #pragma unroll
        for (int i = 0; i < 4; i++)
            #pragma unroll
            for (int j = 0; j < 4; j++)
                ghs[(4 * ty + i) * 196 + 4 * tx + j] = acc[i][j] + bs[4 * tx + j];
    }
    __syncthreads();

    // gate update
    for (int i = tid; i < 32 * 64; i += 384) {
        int r = i >> 6, j = i & 63;
        int n = row0 + r;
        if (n >= NN) continue;
        const float* gi = gi_t + (size_t)n * G3;
        float rg = 1.f / (1.f + __expf(-(gi[j]       + ghs[r * 196 + j])));
        float zg = 1.f / (1.f + __expf(-(gi[64 + j]  + ghs[r * 196 + 64 + j])));
        float ng = tanhf(gi[128 + j] + rg * ghs[r * 196 + 128 + j]);
        float hold = hs[j * 36 + r];
        g_h[(size_t)n * 64 + j] = (1.f - zg) * ng + zg * hold;
    }
}

// ------------------------- decoder: softplus(Z @ Z^T + b), symmetric -------------------------
__device__ __forceinline__ float softplus_f(float x) {
    return fmaxf(x, 0.f) + log1pf(__expf(-fabsf(x)));
}

__global__ __launch_bounds__(256) void k_decoder(const float* __restrict__ Z,
                                                 const float* __restrict__ dec_bias,
                                                 float* __restrict__ out) {
    int bj = blockIdx.x, bi = blockIdx.y;
    if (bi > bj) return;
    extern __shared__ float smem[];
    float* As = smem;
    float* Bs = smem + 64 * 132;
    int tid = threadIdx.x;
    int ri0 = bi * 128, rj0 = bj * 128;
    for (int i = tid; i < 128 * 64; i += 256) {
        int r = i >> 6, k = i & 63;
        As[k * 132 + r] = (ri0 + r < NN) ? Z[(size_t)(ri0 + r) * 64 + k] : 0.f;
        Bs[k * 132 + r] = (rj0 + r < NN) ? Z[(size_t)(rj0 + r) * 64 + k] : 0.f;
    }
    __syncthreads();
    int tx = tid & 15, ty = tid >> 4;
    float acc[8][8] = {};
    #pragma unroll 4
    for (int k = 0; k < 64; k++) {
        const float4* A4 = (const float4*)&As[k * 132];
        const float4* B4 = (const float4*)&Bs[k * 132];
        float4 a0 = A4[ty], a1 = A4[16 + ty];
        float4 b0 = B4[tx], b1 = B4[16 + tx];
        float ar[8] = {a0.x, a0.y, a0.z, a0.w, a1.x, a1.y, a1.z, a1.w};
        float bc[8] = {b0.x, b0.y, b0.z, b0.w, b1.x, b1.y, b1.z, b1.w};
        #pragma unroll
        for (int i = 0; i < 8; i++)
            #pragma unroll
            for (int j = 0; j < 8; j++)
                acc[i][j] += ar[i] * bc[j];
    }
    float db = dec_bias[0];
    int rl[8], cl[8];
    #pragma unroll
    for (int i = 0; i < 8; i++) {
        rl[i] = (i < 4) ? 4 * ty + i : 64 + 4 * ty + (i - 4);
        cl[i] = (i < 4) ? 4 * tx + i : 64 + 4 * tx + (i - 4);
    }
    #pragma unroll
    for (int i = 0; i < 8; i++)
        #pragma unroll
        for (int j = 0; j < 8; j++)
            acc[i][j] = softplus_f(acc[i][j] + db);

    #pragma unroll
    for (int i = 0; i < 8; i++) {
        int r = ri0 + rl[i];
        if (r < NN) {
            #pragma unroll
            for (int j = 0; j < 8; j++) {
                int c = rj0 + cl[j];
                if (c < NN) out[(size_t)r * NN + c] = acc[i][j];
            }
        }
    }
    if (bi != bj) {
        __syncthreads();
        float* St = smem;
        #pragma unroll
        for (int i = 0; i < 8; i++)
            #pragma unroll
            for (int j = 0; j < 8; j++)
                St[cl[j] * 129 + rl[i]] = acc[i][j];
        __syncthreads();
        for (int i = tid; i < 128 * 128; i += 256) {
            int cr = i >> 7, cc = i & 127;
            int r = rj0 + cr, c = ri0 + cc;
            if (r < NN && c < NN) out[(size_t)r * NN + c] = St[cr * 129 + cc];
        }
    }
}

__global__ void k_zcopy(float* __restrict__ o) {
    int i = blockIdx.x * blockDim.x + threadIdx.x;
    if (i < NN * EMB) o[i] = g_h[i];
}

// ------------------------- host orchestration -------------------------
extern "C" void kernel_launch(void* const* d_in, const int* in_sizes, int n_in,
                              void* d_out, int out_size) {
    const float* x   = (const float*)d_in[0];
    const void*  ei  = d_in[1];
    const float* ew  = (const float*)d_in[2];
    const float* W1  = (const float*)d_in[3];
    const float* b1  = (const float*)d_in[4];
    const float* W2  = (const float*)d_in[5];
    const float* b2  = (const float*)d_in[6];
    const float* Wih = (const float*)d_in[7];
    const float* Whh = (const float*)d_in[8];
    const float* bih = (const float*)d_in[9];
    const float* bhh = (const float*)d_in[10];
    const float* db  = (const float*)d_in[11];
    float* out = (float*)d_out;

    float *pAX, *pHW, *pZ, *ph, *pgi;
    cudaGetSymbolAddress((void**)&pAX, g_AX);
    cudaGetSymbolAddress((void**)&pHW, g_HW);
    cudaGetSymbolAddress((void**)&pZ,  g_Z);
    cudaGetSymbolAddress((void**)&ph,  g_h);
    cudaGetSymbolAddress((void**)&pgi, g_gi);

    const size_t sE = (size_t)(64*132 + 128*68 + 64*36 + 128*36 + 128) * 4;       // encfuse ~97KB
    const size_t s3 = (size_t)(64 * (192 + 4) + 64 * 36 + 192) * 4;               // k_gemm<64,192>
    const size_t sG = (size_t)(64*196 + 64*36 + 32*196 + 192) * 4;                // grustep ~85KB
    const size_t sd = (size_t)(2 * 64 * 132) * 4;                                 // decoder

    cudaFuncSetAttribute(k_encfuse, cudaFuncAttributeMaxDynamicSharedMemorySize, (int)sE);
    cudaFuncSetAttribute(k_gemm<64, 192, true, false>,
                         cudaFuncAttributeMaxDynamicSharedMemorySize, (int)s3);
    cudaFuncSetAttribute(k_grustep, cudaFuncAttributeMaxDynamicSharedMemorySize, (int)sG);
    cudaFuncSetAttribute(k_decoder, cudaFuncAttributeMaxDynamicSharedMemorySize, (int)sd);

    // ---- graph-structure setup ----
    k_detect<<<1, 1>>>((const int*)ei);
    k_init<<<(NN * EMB + 255) / 256, 256>>>();
    k_count<<<(EE + 255) / 256, 256>>>(ei, ew);
    k_scan<<<1, 1024>>>();
    k_fill<<<(NNZ + 255) / 256, 256>>>(ei, ew);
    k_norm<<<(NN + 255) / 256, 256>>>();

    const int gM = (NN + 31) / 32;                  // 313 row-tiles
    dim3 spmmGrid((NN * 32 + 255) / 256, TT);

    // ---- encoder (batched over t): AX = A@x ; HW = relu(AX@W1+b1)@W2 ; Z = A@HW + b2 ----
    k_spmm64b<<<spmmGrid, 256>>>(x, pAX, nullptr);
    k_encfuse<<<dim3(gM, TT), 256, sE>>>(pAX, W1, b1, W2, pHW);
    k_spmm64b<<<spmmGrid, 256>>>(pHW, pZ, b2);

    // ---- GRU: gi for all t in one GEMM, then 12 fused steps ----
    k_gemm<64, 192, true, false><<<(TT * NN + 31) / 32, 384, s3>>>(pZ, Wih, bih, pgi, TT * NN);
    for (int t = 0; t < TT; t++)
        k_grustep<<<gM, 384, sG>>>(Whh, bhh, pgi + (size_t)t * NN * G3);

    // ---- decoder ----
    dim3 dg((NN + 127) / 128, (NN + 127) / 128);
    k_decoder<<<dg, 256, sd>>>(ph, db, out);
    k_zcopy<<<(NN * EMB + 255) / 256, 256>>>(out + (size_t)NN * NN);
}